// round 5
// baseline (speedup 1.0000x reference)
#include <cuda_runtime.h>

#define N_USERS 200000
#define N_ITEMS 100000
#define N_NODES 300000
#define N_EDGES 1500000
#define DIM 64
#define BERT 384

#define SCAN_B 1024
#define NB ((N_NODES + SCAN_B - 1) / SCAN_B)   // 293

// Scratch (static device globals — no allocs).
__device__ float g_buf[2][(size_t)N_NODES * DIM];      // x1, x2
__device__ int   g_cnt[N_NODES];                        // degree counts -> cursors
__device__ int   g_rowptr[N_NODES + 1];
__device__ int   g_blocksum[NB];
__device__ int   g_blockoff[NB];
__device__ __align__(16) int2 g_edge[N_EDGES];          // {col, val bits}

// ---------------------------------------------------------------------------
// CSR build: zero counts -> histogram -> 2-level exclusive scan -> scatter
// ---------------------------------------------------------------------------
__global__ void zero_cnt_k()
{
    int i = blockIdx.x * blockDim.x + threadIdx.x;
    if (i < N_NODES) g_cnt[i] = 0;
}

__global__ void hist_k(const int* __restrict__ rows)
{
    int e = blockIdx.x * blockDim.x + threadIdx.x;
    if (e < N_EDGES) atomicAdd(&g_cnt[rows[e]], 1);
}

__global__ __launch_bounds__(SCAN_B) void scan1_k()
{
    __shared__ int sh[SCAN_B];
    int i = blockIdx.x * SCAN_B + threadIdx.x;
    int v = (i < N_NODES) ? g_cnt[i] : 0;
    int orig = v;
    sh[threadIdx.x] = v;
    __syncthreads();
#pragma unroll
    for (int d = 1; d < SCAN_B; d <<= 1) {
        int t = (threadIdx.x >= d) ? sh[threadIdx.x - d] : 0;
        __syncthreads();
        sh[threadIdx.x] += t;
        __syncthreads();
    }
    if (i < N_NODES) g_rowptr[i] = sh[threadIdx.x] - orig;       // exclusive in-block
    if (threadIdx.x == SCAN_B - 1) g_blocksum[blockIdx.x] = sh[threadIdx.x];
}

__global__ __launch_bounds__(512) void scan2_k()
{
    __shared__ int sh[512];
    int t = threadIdx.x;
    int v = (t < NB) ? g_blocksum[t] : 0;
    int orig = v;
    sh[t] = v;
    __syncthreads();
#pragma unroll
    for (int d = 1; d < 512; d <<= 1) {
        int u = (t >= d) ? sh[t - d] : 0;
        __syncthreads();
        sh[t] += u;
        __syncthreads();
    }
    if (t < NB) g_blockoff[t] = sh[t] - orig;                    // exclusive
    if (t == 0) g_rowptr[N_NODES] = N_EDGES;
}

__global__ void scan3_k()
{
    int i = blockIdx.x * blockDim.x + threadIdx.x;
    if (i < N_NODES) {
        int r = g_rowptr[i] + g_blockoff[i >> 10];
        g_rowptr[i] = r;
        g_cnt[i] = r;                                            // cursor for scatter
    }
}

__global__ void scatter_k(const int* __restrict__ rows,
                          const int* __restrict__ cols,
                          const float* __restrict__ vals)
{
    int e = blockIdx.x * blockDim.x + threadIdx.x;
    if (e >= N_EDGES) return;
    int r = rows[e];
    int p = atomicAdd(&g_cnt[r], 1);
    g_edge[p] = make_int2(cols[e], __float_as_int(vals[e]));
}

// ---------------------------------------------------------------------------
// User init: out[u] = user_emb[u] + gender_emb[g] + age_emb[a]
// ---------------------------------------------------------------------------
__global__ void init_users_k(const float4* __restrict__ ue,
                             const float4* __restrict__ ge,
                             const float4* __restrict__ ae,
                             const int* __restrict__ ug,
                             const int* __restrict__ ua,
                             float4* __restrict__ out)
{
    int idx = blockIdx.x * blockDim.x + threadIdx.x;
    if (idx >= N_USERS * 16) return;
    int u = idx >> 4, s = idx & 15;
    int g = ug[u];
    int a = ua[u];
    float4 r = ue[idx];
    float4 gv = ge[g * 16 + s];
    float4 av = ae[a * 16 + s];
    r.x += gv.x + av.x; r.y += gv.y + av.y;
    r.z += gv.z + av.z; r.w += gv.w + av.w;
    out[idx] = r;
}

// ---------------------------------------------------------------------------
// Item init GEMM, fp32 packed (fma.rn.f32x2), double-buffered.
// BM=128, BN=64 (full), BK=16, 128 threads, per-thread 8 rows x 8 cols.
// B duplicated in smem (stride-20 word groups -> conflict-free packed LDS.128).
// Register-prefetch of next tile's globals overlaps compute; 1 sync per tile.
// ---------------------------------------------------------------------------
#define GBM 128
#define GBK 16
#define NTILES (BERT / GBK)     // 24
#define BS_STRIDE 20            // words per 8-col dup group (16 data + 4 pad)

#define FMA2(acc, a, b) \
    asm("fma.rn.f32x2 %0, %1, %2, %3;" : "=l"(acc) : "l"(a), "l"(b), "l"(acc))

__device__ __forceinline__ float2 unpack2(unsigned long long u)
{
    float2 f;
    asm("mov.b64 {%0, %1}, %2;" : "=f"(f.x), "=f"(f.y) : "l"(u));
    return f;
}

__device__ __forceinline__ unsigned long long dup2(float f)
{
    unsigned long long u;
    asm("mov.b64 %0, {%1, %1};" : "=l"(u) : "f"(f));
    return u;
}

__global__ __launch_bounds__(128, 4) void item_gemm_k(
    const float* __restrict__ bert,      // [N_ITEMS, 384]
    const float* __restrict__ W,         // [64, 384]
    const float4* __restrict__ ie,
    const float4* __restrict__ ce,
    const int* __restrict__ cat,
    float4* __restrict__ out)
{
    __shared__ __align__(16) float As[2][GBK][GBM + 4];       // [buf][k][m]
    __shared__ __align__(16) float Bs[2][GBK][8 * BS_STRIDE]; // [buf][k][dup group]

    int t  = threadIdx.x;
    int tx = t & 7;           // col group: cols tx*8 .. tx*8+7
    int ty = t >> 3;          // row group: rows ty*8 .. ty*8+7
    int rb = blockIdx.x * GBM;

    unsigned long long acc2[4][8];       // [row-pair][col]
#pragma unroll
    for (int p = 0; p < 4; p++)
#pragma unroll
        for (int c = 0; c < 8; c++) acc2[p][c] = 0ull;

    // Per-tile loads: A = 512 float4 (4/thread), B = 256 float4 (2/thread).
    // f4 slot q: m(or n) = q>>2, kq = q&3.
    float4 va[4], vb[2];

#define LOAD_A(k0)                                                          \
    {                                                                       \
        _Pragma("unroll")                                                   \
        for (int i = 0; i < 4; i++) {                                       \
            int q = i * 128 + t;                                            \
            int m = q >> 2, kq = q & 3;                                     \
            va[i] = (rb + m < N_ITEMS)                                      \
                ? *reinterpret_cast<const float4*>(                         \
                      bert + (size_t)(rb + m) * BERT + (k0) + kq * 4)       \
                : make_float4(0.f, 0.f, 0.f, 0.f);                          \
        }                                                                   \
    }
#define LOAD_B(k0)                                                          \
    {                                                                       \
        _Pragma("unroll")                                                   \
        for (int i = 0; i < 2; i++) {                                       \
            int q = i * 128 + t;                                            \
            int n = q >> 2, kq = q & 3;                                     \
            vb[i] = *reinterpret_cast<const float4*>(                       \
                        W + (size_t)n * BERT + (k0) + kq * 4);              \
        }                                                                   \
    }
#define STORE_AB(buf)                                                       \
    {                                                                       \
        _Pragma("unroll")                                                   \
        for (int i = 0; i < 4; i++) {                                       \
            int q = i * 128 + t;                                            \
            int m = q >> 2, kq = q & 3;                                     \
            As[buf][kq * 4 + 0][m] = va[i].x;                               \
            As[buf][kq * 4 + 1][m] = va[i].y;                               \
            As[buf][kq * 4 + 2][m] = va[i].z;                               \
            As[buf][kq * 4 + 3][m] = va[i].w;                               \
        }                                                                   \
        _Pragma("unroll")                                                   \
        for (int i = 0; i < 2; i++) {                                       \
            int q = i * 128 + t;                                            \
            int n = q >> 2, kq = q & 3;                                     \
            int w = (n >> 3) * BS_STRIDE + (n & 7) * 2;                     \
            unsigned long long* bp;                                         \
            bp = reinterpret_cast<unsigned long long*>(&Bs[buf][kq*4+0][w]);\
            *bp = dup2(vb[i].x);                                            \
            bp = reinterpret_cast<unsigned long long*>(&Bs[buf][kq*4+1][w]);\
            *bp = dup2(vb[i].y);                                            \
            bp = reinterpret_cast<unsigned long long*>(&Bs[buf][kq*4+2][w]);\
            *bp = dup2(vb[i].z);                                            \
            bp = reinterpret_cast<unsigned long long*>(&Bs[buf][kq*4+3][w]);\
            *bp = dup2(vb[i].w);                                            \
        }                                                                   \
    }

    LOAD_A(0); LOAD_B(0);
    STORE_AB(0);
    __syncthreads();

#pragma unroll 1
    for (int tile = 0; tile < NTILES; tile++) {
        int buf = tile & 1;
        if (tile + 1 < NTILES) { LOAD_A((tile + 1) * GBK); LOAD_B((tile + 1) * GBK); }

#pragma unroll
        for (int k = 0; k < GBK; k++) {
            ulonglong2 a0 = *reinterpret_cast<const ulonglong2*>(&As[buf][k][ty * 8]);
            ulonglong2 a1 = *reinterpret_cast<const ulonglong2*>(&As[buf][k][ty * 8 + 4]);
            const float* brow = &Bs[buf][k][tx * BS_STRIDE];
            ulonglong2 b0 = *reinterpret_cast<const ulonglong2*>(brow);
            ulonglong2 b1 = *reinterpret_cast<const ulonglong2*>(brow + 8);
            ulonglong2 b2 = *reinterpret_cast<const ulonglong2*>(brow + 16)
                ; // words 16..19 hold cols 8,9 region? no: see layout note
            (void)b2;
            // Layout: group tx holds 16 dup words (cols tx*8..tx*8+7) at
            // words [tx*20, tx*20+16).  Read as 4x LDS.128:
            ulonglong2 c0 = *reinterpret_cast<const ulonglong2*>(brow + 0);
            ulonglong2 c1 = *reinterpret_cast<const ulonglong2*>(brow + 4);
            ulonglong2 c2 = *reinterpret_cast<const ulonglong2*>(brow + 8);
            ulonglong2 c3 = *reinterpret_cast<const ulonglong2*>(brow + 12);
            (void)b0; (void)b1;
            unsigned long long ap[4] = {a0.x, a0.y, a1.x, a1.y};
            unsigned long long bp[8] = {c0.x, c0.y, c1.x, c1.y,
                                        c2.x, c2.y, c3.x, c3.y};
#pragma unroll
            for (int p = 0; p < 4; p++)
#pragma unroll
                for (int c = 0; c < 8; c++)
                    FMA2(acc2[p][c], ap[p], bp[c]);
        }

        if (tile + 1 < NTILES) STORE_AB(buf ^ 1);
        __syncthreads();
    }

    // Epilogue: + item_emb + cat_emb.  Rows rb+ty*8+{0..7}, f4 segs 2tx, 2tx+1.
#pragma unroll
    for (int p = 0; p < 4; p++) {
        float2 c0 = unpack2(acc2[p][0]);
        float2 c1 = unpack2(acc2[p][1]);
        float2 c2 = unpack2(acc2[p][2]);
        float2 c3 = unpack2(acc2[p][3]);
        float2 c4 = unpack2(acc2[p][4]);
        float2 c5 = unpack2(acc2[p][5]);
        float2 c6 = unpack2(acc2[p][6]);
        float2 c7 = unpack2(acc2[p][7]);
        int r0 = rb + ty * 8 + 2 * p;
#pragma unroll
        for (int h = 0; h < 2; h++) {
            int row = r0 + h;
            if (row < N_ITEMS) {
                int cc = cat[row];
                int s0 = tx * 2, s1 = tx * 2 + 1;
                float4 e0 = ie[row * 16 + s0];
                float4 e1 = ie[row * 16 + s1];
                float4 v0 = ce[cc * 16 + s0];
                float4 v1 = ce[cc * 16 + s1];
                float4 o0, o1;
                o0.x = (h ? c0.y : c0.x) + e0.x + v0.x;
                o0.y = (h ? c1.y : c1.x) + e0.y + v0.y;
                o0.z = (h ? c2.y : c2.x) + e0.z + v0.z;
                o0.w = (h ? c3.y : c3.x) + e0.w + v0.w;
                o1.x = (h ? c4.y : c4.x) + e1.x + v1.x;
                o1.y = (h ? c5.y : c5.x) + e1.y + v1.y;
                o1.z = (h ? c6.y : c6.x) + e1.z + v1.z;
                o1.w = (h ? c7.y : c7.x) + e1.w + v1.w;
                size_t ob = (size_t)(N_USERS + row) * 16;
                out[ob + s0] = o0;
                out[ob + s1] = o1;
            }
        }
    }
}

// ---------------------------------------------------------------------------
// CSR gather SpMM: one warp per row.  16 lanes per edge cover the full
// 64-float row (coalesced 256B); two edges in flight per iteration
// (lanes 0-15 -> edge j, lanes 16-31 -> edge j+1).  shfl-xor(16) reduce.
// No divergence across rows, no atomics, no pre-zeroing.
// ---------------------------------------------------------------------------
__device__ __forceinline__ float4 spmm_warp_row(const float4* __restrict__ x,
                                                int r, int half, int s)
{
    int beg = __ldg(&g_rowptr[r]);
    int end = __ldg(&g_rowptr[r + 1]);
    float4 acc = make_float4(0.f, 0.f, 0.f, 0.f);
#pragma unroll 2
    for (int j = beg + half; j < end; j += 2) {
        int2 e = __ldg(&g_edge[j]);
        float v = __int_as_float(e.y);
        float4 xv = __ldg(&x[e.x * 16 + s]);
        acc.x += v * xv.x; acc.y += v * xv.y;
        acc.z += v * xv.z; acc.w += v * xv.w;
    }
    acc.x += __shfl_xor_sync(0xFFFFFFFFu, acc.x, 16);
    acc.y += __shfl_xor_sync(0xFFFFFFFFu, acc.y, 16);
    acc.z += __shfl_xor_sync(0xFFFFFFFFu, acc.z, 16);
    acc.w += __shfl_xor_sync(0xFFFFFFFFu, acc.w, 16);
    return acc;
}

__global__ __launch_bounds__(256) void spmm_gather_k(const float4* __restrict__ x,
                                                     float4* __restrict__ y)
{
    int w = (blockIdx.x * 256 + threadIdx.x) >> 5;
    if (w >= N_NODES) return;
    int lane = threadIdx.x & 31;
    int half = lane >> 4, s = lane & 15;
    float4 acc = spmm_warp_row(x, w, half, s);
    if (half == 0) y[w * 16 + s] = acc;
}

// Last layer fused with the mean: out = (x0 + x1 + x2 + A*x2) / 4
__global__ __launch_bounds__(256) void spmm_final_k(const float4* __restrict__ x,  // x2
                                                    const float4* __restrict__ b1, // x1
                                                    float4* __restrict__ out)      // x0 in, result out
{
    int w = (blockIdx.x * 256 + threadIdx.x) >> 5;
    if (w >= N_NODES) return;
    int lane = threadIdx.x & 31;
    int half = lane >> 4, s = lane & 15;
    float4 acc = spmm_warp_row(x, w, half, s);
    if (half == 0) {
        int o = w * 16 + s;
        float4 a0 = out[o];
        float4 a1 = b1[o];
        float4 a2 = x[o];
        float4 v;
        v.x = (a0.x + a1.x + a2.x + acc.x) * 0.25f;
        v.y = (a0.y + a1.y + a2.y + acc.y) * 0.25f;
        v.z = (a0.z + a1.z + a2.z + acc.z) * 0.25f;
        v.w = (a0.w + a1.w + a2.w + acc.w) * 0.25f;
        out[o] = v;
    }
}

// ---------------------------------------------------------------------------
extern "C" void kernel_launch(void* const* d_in, const int* in_sizes, int n_in,
                              void* d_out, int out_size)
{
    const float* user_emb    = (const float*)d_in[0];
    const float* item_emb    = (const float*)d_in[1];
    const float* gender_emb  = (const float*)d_in[2];
    const float* age_emb     = (const float*)d_in[3];
    const float* cat_emb     = (const float*)d_in[4];
    const float* bert_proj_w = (const float*)d_in[5];
    const float* item_bert   = (const float*)d_in[6];
    const float* adj_val     = (const float*)d_in[7];
    const int*   user_gender = (const int*)d_in[8];
    const int*   user_age    = (const int*)d_in[9];
    const int*   item_cat    = (const int*)d_in[10];
    const int*   adj_row     = (const int*)d_in[11];
    const int*   adj_col     = (const int*)d_in[12];
    float4* out = (float4*)d_out;

    (void)in_sizes; (void)n_in; (void)out_size;

    float4* buf0; cudaGetSymbolAddress((void**)&buf0, g_buf);      // x1
    float4* buf1 = buf0 + (size_t)N_NODES * 16;                    // x2

    const int eg = (N_EDGES + 255) / 256;
    const int ng = (N_NODES + 255) / 256;

    // CSR build, with item_gemm at launch index 3 (ncu profiles index 3).
    zero_cnt_k<<<ng, 256>>>();                                     // 0
    hist_k<<<eg, 256>>>(adj_row);                                  // 1
    scan1_k<<<NB, SCAN_B>>>();                                     // 2
    item_gemm_k<<<(N_ITEMS + GBM - 1) / GBM, 128>>>(               // 3 <- profiled
        item_bert, bert_proj_w, (const float4*)item_emb,
        (const float4*)cat_emb, item_cat, out);
    scan2_k<<<1, 512>>>();                                         // 4
    scan3_k<<<ng, 256>>>();                                        // 5
    scatter_k<<<eg, 256>>>(adj_row, adj_col, adj_val);             // 6
    init_users_k<<<(N_USERS * 16 + 255) / 256, 256>>>(             // 7
        (const float4*)user_emb, (const float4*)gender_emb,
        (const float4*)age_emb, user_gender, user_age, out);

    const int sg = (N_NODES * 32 + 255) / 256;     // one warp per row
    spmm_gather_k<<<sg, 256>>>(out,  buf0);          // x1 = A x0
    spmm_gather_k<<<sg, 256>>>(buf0, buf1);          // x2 = A x1
    spmm_final_k<<<sg, 256>>>(buf1, buf0, out);      // out = (x0+x1+x2+A x2)/4
}

// round 7
// speedup vs baseline: 1.5300x; 1.5300x over previous
#include <cuda_runtime.h>

#define N_USERS 200000
#define N_ITEMS 100000
#define N_NODES 300000
#define N_EDGES 1500000
#define DIM 64
#define BERT 384

#define SCAN_B 1024
#define NB ((N_NODES + SCAN_B - 1) / SCAN_B)   // 293

// Scratch (static device globals — no allocs).
__device__ float g_buf[2][(size_t)N_NODES * DIM];      // x1, x2
__device__ int   g_cnt[N_NODES];                        // degree counts -> cursors
__device__ int   g_rowptr[N_NODES + 1];
__device__ int   g_blocksum[NB];
__device__ int   g_blockoff[NB];
__device__ __align__(16) int2 g_edge[N_EDGES];          // {col, val bits}

// ---------------------------------------------------------------------------
// CSR build: zero counts -> histogram -> 2-level exclusive scan -> scatter
// ---------------------------------------------------------------------------
__global__ void zero_cnt_k()
{
    int i = blockIdx.x * blockDim.x + threadIdx.x;
    if (i < N_NODES) g_cnt[i] = 0;
}

__global__ void hist_k(const int* __restrict__ rows)
{
    int e = blockIdx.x * blockDim.x + threadIdx.x;
    if (e < N_EDGES) atomicAdd(&g_cnt[rows[e]], 1);
}

__global__ __launch_bounds__(SCAN_B) void scan1_k()
{
    __shared__ int sh[SCAN_B];
    int i = blockIdx.x * SCAN_B + threadIdx.x;
    int v = (i < N_NODES) ? g_cnt[i] : 0;
    int orig = v;
    sh[threadIdx.x] = v;
    __syncthreads();
#pragma unroll
    for (int d = 1; d < SCAN_B; d <<= 1) {
        int t = (threadIdx.x >= d) ? sh[threadIdx.x - d] : 0;
        __syncthreads();
        sh[threadIdx.x] += t;
        __syncthreads();
    }
    if (i < N_NODES) g_rowptr[i] = sh[threadIdx.x] - orig;       // exclusive in-block
    if (threadIdx.x == SCAN_B - 1) g_blocksum[blockIdx.x] = sh[threadIdx.x];
}

__global__ __launch_bounds__(512) void scan2_k()
{
    __shared__ int sh[512];
    int t = threadIdx.x;
    int v = (t < NB) ? g_blocksum[t] : 0;
    int orig = v;
    sh[t] = v;
    __syncthreads();
#pragma unroll
    for (int d = 1; d < 512; d <<= 1) {
        int u = (t >= d) ? sh[t - d] : 0;
        __syncthreads();
        sh[t] += u;
        __syncthreads();
    }
    if (t < NB) g_blockoff[t] = sh[t] - orig;                    // exclusive
    if (t == 0) g_rowptr[N_NODES] = N_EDGES;
}

__global__ void scan3_k()
{
    int i = blockIdx.x * blockDim.x + threadIdx.x;
    if (i < N_NODES) {
        int r = g_rowptr[i] + g_blockoff[i >> 10];
        g_rowptr[i] = r;
        g_cnt[i] = r;                                            // cursor for scatter
    }
}

__global__ void scatter_k(const int* __restrict__ rows,
                          const int* __restrict__ cols,
                          const float* __restrict__ vals)
{
    int e = blockIdx.x * blockDim.x + threadIdx.x;
    if (e >= N_EDGES) return;
    int r = rows[e];
    int p = atomicAdd(&g_cnt[r], 1);
    g_edge[p] = make_int2(cols[e], __float_as_int(vals[e]));
}

// ---------------------------------------------------------------------------
// User init: out[u] = user_emb[u] + gender_emb[g] + age_emb[a]
// ---------------------------------------------------------------------------
__global__ void init_users_k(const float4* __restrict__ ue,
                             const float4* __restrict__ ge,
                             const float4* __restrict__ ae,
                             const int* __restrict__ ug,
                             const int* __restrict__ ua,
                             float4* __restrict__ out)
{
    int idx = blockIdx.x * blockDim.x + threadIdx.x;
    if (idx >= N_USERS * 16) return;
    int u = idx >> 4, s = idx & 15;
    int g = ug[u];
    int a = ua[u];
    float4 r = ue[idx];
    float4 gv = ge[g * 16 + s];
    float4 av = ae[a * 16 + s];
    r.x += gv.x + av.x; r.y += gv.y + av.y;
    r.z += gv.z + av.z; r.w += gv.w + av.w;
    out[idx] = r;
}

// ---------------------------------------------------------------------------
// Item init GEMM, fp32 packed (fma.rn.f32x2).
// R3 mainloop (BM=128, BK=32, 128 threads, 8x8 per-thread tile, PACK2 for B)
// + double-buffered smem + register prefetch of next tile's globals.
// One __syncthreads per tile; no launch_bounds reg cap (avoids R5's spills).
// ---------------------------------------------------------------------------
#define GBM 128
#define GBK 32
#define NT (BERT / GBK)      // 12

#define FMA2(acc, a, b) \
    asm("fma.rn.f32x2 %0, %1, %2, %3;" : "=l"(acc) : "l"(a), "l"(b), "l"(acc))
#define PACK2(u, f) \
    asm("mov.b64 %0, {%1, %1};" : "=l"(u) : "f"(f))

__device__ __forceinline__ float2 unpack2(unsigned long long u)
{
    float2 f;
    asm("mov.b64 {%0, %1}, %2;" : "=f"(f.x), "=f"(f.y) : "l"(u));
    return f;
}

__global__ __launch_bounds__(128) void item_gemm_k(
    const float* __restrict__ bert,      // [N_ITEMS, 384]
    const float* __restrict__ W,         // [64, 384]
    const float4* __restrict__ ie,
    const float4* __restrict__ ce,
    const int* __restrict__ cat,
    float4* __restrict__ out)
{
    __shared__ __align__(16) float As[2][GBK][GBM + 4];   // [buf][k][m]
    __shared__ __align__(16) float Bs[2][GBK][64 + 4];    // [buf][k][n]

    int t  = threadIdx.x;
    int tx = t & 7;           // col group: cols tx*8 .. tx*8+7
    int ty = t >> 3;          // row group: rows ty*8 .. ty*8+7
    int rb = blockIdx.x * GBM;

    unsigned long long acc2[4][8];       // [row-pair][col]
#pragma unroll
    for (int p = 0; p < 4; p++)
#pragma unroll
        for (int c = 0; c < 8; c++) acc2[p][c] = 0ull;

    // Prefetch registers: A = 1024 f4 (8/thread), B = 512 f4 (4/thread).
    float4 va[8], vb[4];

#define LOAD_AB(k0)                                                         \
    {                                                                       \
        _Pragma("unroll")                                                   \
        for (int i = 0; i < 8; i++) {                                       \
            int q = i * 128 + t;                                            \
            int m = q >> 3, kq = q & 7;                                     \
            va[i] = (rb + m < N_ITEMS)                                      \
                ? *reinterpret_cast<const float4*>(                         \
                      bert + (size_t)(rb + m) * BERT + (k0) + kq * 4)       \
                : make_float4(0.f, 0.f, 0.f, 0.f);                          \
        }                                                                   \
        _Pragma("unroll")                                                   \
        for (int i = 0; i < 4; i++) {                                       \
            int q = i * 128 + t;                                            \
            int n = q >> 3, kq = q & 7;                                     \
            vb[i] = *reinterpret_cast<const float4*>(                       \
                        W + (size_t)n * BERT + (k0) + kq * 4);              \
        }                                                                   \
    }
#define STORE_AB(buf)                                                       \
    {                                                                       \
        _Pragma("unroll")                                                   \
        for (int i = 0; i < 8; i++) {                                       \
            int q = i * 128 + t;                                            \
            int m = q >> 3, kq = q & 7;                                     \
            As[buf][kq * 4 + 0][m] = va[i].x;                               \
            As[buf][kq * 4 + 1][m] = va[i].y;                               \
            As[buf][kq * 4 + 2][m] = va[i].z;                               \
            As[buf][kq * 4 + 3][m] = va[i].w;                               \
        }                                                                   \
        _Pragma("unroll")                                                   \
        for (int i = 0; i < 4; i++) {                                       \
            int q = i * 128 + t;                                            \
            int n = q >> 3, kq = q & 7;                                     \
            Bs[buf][kq * 4 + 0][n] = vb[i].x;                               \
            Bs[buf][kq * 4 + 1][n] = vb[i].y;                               \
            Bs[buf][kq * 4 + 2][n] = vb[i].z;                               \
            Bs[buf][kq * 4 + 3][n] = vb[i].w;                               \
        }                                                                   \
    }

    LOAD_AB(0);
    STORE_AB(0);
    __syncthreads();

#pragma unroll 1
    for (int tile = 0; tile < NT; tile++) {
        int buf = tile & 1;
        if (tile + 1 < NT) LOAD_AB((tile + 1) * GBK);   // LDG overlaps compute

#pragma unroll
        for (int k = 0; k < GBK; k++) {
            ulonglong2 a0 = *reinterpret_cast<const ulonglong2*>(&As[buf][k][ty * 8]);
            ulonglong2 a1 = *reinterpret_cast<const ulonglong2*>(&As[buf][k][ty * 8 + 4]);
            float4 b0 = *reinterpret_cast<const float4*>(&Bs[buf][k][tx * 8]);
            float4 b1 = *reinterpret_cast<const float4*>(&Bs[buf][k][tx * 8 + 4]);
            unsigned long long ap[4] = {a0.x, a0.y, a1.x, a1.y};
            unsigned long long bp[8];
            PACK2(bp[0], b0.x); PACK2(bp[1], b0.y);
            PACK2(bp[2], b0.z); PACK2(bp[3], b0.w);
            PACK2(bp[4], b1.x); PACK2(bp[5], b1.y);
            PACK2(bp[6], b1.z); PACK2(bp[7], b1.w);
#pragma unroll
            for (int p = 0; p < 4; p++)
#pragma unroll
                for (int c = 0; c < 8; c++)
                    FMA2(acc2[p][c], ap[p], bp[c]);
        }

        // Safe: buf^1 was fully consumed before the sync that opened this tile.
        if (tile + 1 < NT) STORE_AB(buf ^ 1);
        __syncthreads();
    }

    // Epilogue: + item_emb + cat_emb.  Rows rb+ty*8+{0..7}, f4 segs 2tx, 2tx+1.
#pragma unroll
    for (int p = 0; p < 4; p++) {
        float2 c0 = unpack2(acc2[p][0]);
        float2 c1 = unpack2(acc2[p][1]);
        float2 c2 = unpack2(acc2[p][2]);
        float2 c3 = unpack2(acc2[p][3]);
        float2 c4 = unpack2(acc2[p][4]);
        float2 c5 = unpack2(acc2[p][5]);
        float2 c6 = unpack2(acc2[p][6]);
        float2 c7 = unpack2(acc2[p][7]);
        int r0 = rb + ty * 8 + 2 * p;
#pragma unroll
        for (int h = 0; h < 2; h++) {
            int row = r0 + h;
            if (row < N_ITEMS) {
                int cc = cat[row];
                int s0 = tx * 2, s1 = tx * 2 + 1;
                float4 e0 = ie[row * 16 + s0];
                float4 e1 = ie[row * 16 + s1];
                float4 v0 = ce[cc * 16 + s0];
                float4 v1 = ce[cc * 16 + s1];
                float4 o0, o1;
                o0.x = (h ? c0.y : c0.x) + e0.x + v0.x;
                o0.y = (h ? c1.y : c1.x) + e0.y + v0.y;
                o0.z = (h ? c2.y : c2.x) + e0.z + v0.z;
                o0.w = (h ? c3.y : c3.x) + e0.w + v0.w;
                o1.x = (h ? c4.y : c4.x) + e1.x + v1.x;
                o1.y = (h ? c5.y : c5.x) + e1.y + v1.y;
                o1.z = (h ? c6.y : c6.x) + e1.z + v1.z;
                o1.w = (h ? c7.y : c7.x) + e1.w + v1.w;
                size_t ob = (size_t)(N_USERS + row) * 16;
                out[ob + s0] = o0;
                out[ob + s1] = o1;
            }
        }
    }
}

// ---------------------------------------------------------------------------
// CSR gather SpMM (R4 best): 8 lanes per row, each lane owns 2 float4
// segments -> 2 independent loads per edge; size-stepped unrolling (4/2/1)
// keeps up to 8 x-loads in flight.
// ---------------------------------------------------------------------------
struct f4x2 { float4 a, b; };

__device__ __forceinline__ f4x2 spmm_row8(const float4* __restrict__ x,
                                          int r, int s)
{
    int beg = __ldg(&g_rowptr[r]);
    int end = __ldg(&g_rowptr[r + 1]);
    float4 acc0 = make_float4(0.f, 0.f, 0.f, 0.f);
    float4 acc1 = make_float4(0.f, 0.f, 0.f, 0.f);
    int jj = beg;
    while (jj < end) {
        int n = end - jj;
        if (n >= 4) {
            int2 e0 = __ldg(&g_edge[jj + 0]);
            int2 e1 = __ldg(&g_edge[jj + 1]);
            int2 e2 = __ldg(&g_edge[jj + 2]);
            int2 e3 = __ldg(&g_edge[jj + 3]);
            float4 p0 = __ldg(&x[e0.x * 16 + 2 * s]);
            float4 q0 = __ldg(&x[e0.x * 16 + 2 * s + 1]);
            float4 p1 = __ldg(&x[e1.x * 16 + 2 * s]);
            float4 q1 = __ldg(&x[e1.x * 16 + 2 * s + 1]);
            float4 p2 = __ldg(&x[e2.x * 16 + 2 * s]);
            float4 q2 = __ldg(&x[e2.x * 16 + 2 * s + 1]);
            float4 p3 = __ldg(&x[e3.x * 16 + 2 * s]);
            float4 q3 = __ldg(&x[e3.x * 16 + 2 * s + 1]);
            float v0 = __int_as_float(e0.y);
            float v1 = __int_as_float(e1.y);
            float v2 = __int_as_float(e2.y);
            float v3 = __int_as_float(e3.y);
            acc0.x += v0 * p0.x; acc0.y += v0 * p0.y; acc0.z += v0 * p0.z; acc0.w += v0 * p0.w;
            acc1.x += v0 * q0.x; acc1.y += v0 * q0.y; acc1.z += v0 * q0.z; acc1.w += v0 * q0.w;
            acc0.x += v1 * p1.x; acc0.y += v1 * p1.y; acc0.z += v1 * p1.z; acc0.w += v1 * p1.w;
            acc1.x += v1 * q1.x; acc1.y += v1 * q1.y; acc1.z += v1 * q1.z; acc1.w += v1 * q1.w;
            acc0.x += v2 * p2.x; acc0.y += v2 * p2.y; acc0.z += v2 * p2.z; acc0.w += v2 * p2.w;
            acc1.x += v2 * q2.x; acc1.y += v2 * q2.y; acc1.z += v2 * q2.z; acc1.w += v2 * q2.w;
            acc0.x += v3 * p3.x; acc0.y += v3 * p3.y; acc0.z += v3 * p3.z; acc0.w += v3 * p3.w;
            acc1.x += v3 * q3.x; acc1.y += v3 * q3.y; acc1.z += v3 * q3.z; acc1.w += v3 * q3.w;
            jj += 4;
        } else if (n >= 2) {
            int2 e0 = __ldg(&g_edge[jj + 0]);
            int2 e1 = __ldg(&g_edge[jj + 1]);
            float4 p0 = __ldg(&x[e0.x * 16 + 2 * s]);
            float4 q0 = __ldg(&x[e0.x * 16 + 2 * s + 1]);
            float4 p1 = __ldg(&x[e1.x * 16 + 2 * s]);
            float4 q1 = __ldg(&x[e1.x * 16 + 2 * s + 1]);
            float v0 = __int_as_float(e0.y);
            float v1 = __int_as_float(e1.y);
            acc0.x += v0 * p0.x; acc0.y += v0 * p0.y; acc0.z += v0 * p0.z; acc0.w += v0 * p0.w;
            acc1.x += v0 * q0.x; acc1.y += v0 * q0.y; acc1.z += v0 * q0.z; acc1.w += v0 * q0.w;
            acc0.x += v1 * p1.x; acc0.y += v1 * p1.y; acc0.z += v1 * p1.z; acc0.w += v1 * p1.w;
            acc1.x += v1 * q1.x; acc1.y += v1 * q1.y; acc1.z += v1 * q1.z; acc1.w += v1 * q1.w;
            jj += 2;
        } else {
            int2 e0 = __ldg(&g_edge[jj]);
            float4 p0 = __ldg(&x[e0.x * 16 + 2 * s]);
            float4 q0 = __ldg(&x[e0.x * 16 + 2 * s + 1]);
            float v0 = __int_as_float(e0.y);
            acc0.x += v0 * p0.x; acc0.y += v0 * p0.y; acc0.z += v0 * p0.z; acc0.w += v0 * p0.w;
            acc1.x += v0 * q0.x; acc1.y += v0 * q0.y; acc1.z += v0 * q0.z; acc1.w += v0 * q0.w;
            jj += 1;
        }
    }
    f4x2 r2; r2.a = acc0; r2.b = acc1;
    return r2;
}

__global__ __launch_bounds__(256) void spmm_gather_k(const float4* __restrict__ x,
                                                     float4* __restrict__ y)
{
    int tid = blockIdx.x * blockDim.x + threadIdx.x;
    int r = tid >> 3;
    if (r >= N_NODES) return;
    int s = tid & 7;
    f4x2 acc = spmm_row8(x, r, s);
    y[r * 16 + 2 * s]     = acc.a;
    y[r * 16 + 2 * s + 1] = acc.b;
}

// Last layer fused with the mean: out = (x0 + x1 + x2 + A*x2) / 4
__global__ __launch_bounds__(256) void spmm_final_k(const float4* __restrict__ x,  // x2
                                                    const float4* __restrict__ b1, // x1
                                                    float4* __restrict__ out)      // x0 in, result out
{
    int tid = blockIdx.x * blockDim.x + threadIdx.x;
    int r = tid >> 3;
    if (r >= N_NODES) return;
    int s = tid & 7;
    f4x2 acc = spmm_row8(x, r, s);
#pragma unroll
    for (int h = 0; h < 2; h++) {
        int o = r * 16 + 2 * s + h;
        float4 ac = h ? acc.b : acc.a;
        float4 a0 = out[o];
        float4 a1 = b1[o];
        float4 a2 = x[o];
        float4 v;
        v.x = (a0.x + a1.x + a2.x + ac.x) * 0.25f;
        v.y = (a0.y + a1.y + a2.y + ac.y) * 0.25f;
        v.z = (a0.z + a1.z + a2.z + ac.z) * 0.25f;
        v.w = (a0.w + a1.w + a2.w + ac.w) * 0.25f;
        out[o] = v;
    }
}

// ---------------------------------------------------------------------------
extern "C" void kernel_launch(void* const* d_in, const int* in_sizes, int n_in,
                              void* d_out, int out_size)
{
    const float* user_emb    = (const float*)d_in[0];
    const float* item_emb    = (const float*)d_in[1];
    const float* gender_emb  = (const float*)d_in[2];
    const float* age_emb     = (const float*)d_in[3];
    const float* cat_emb     = (const float*)d_in[4];
    const float* bert_proj_w = (const float*)d_in[5];
    const float* item_bert   = (const float*)d_in[6];
    const float* adj_val     = (const float*)d_in[7];
    const int*   user_gender = (const int*)d_in[8];
    const int*   user_age    = (const int*)d_in[9];
    const int*   item_cat    = (const int*)d_in[10];
    const int*   adj_row     = (const int*)d_in[11];
    const int*   adj_col     = (const int*)d_in[12];
    float4* out = (float4*)d_out;

    (void)in_sizes; (void)n_in; (void)out_size;

    float4* buf0; cudaGetSymbolAddress((void**)&buf0, g_buf);      // x1
    float4* buf1 = buf0 + (size_t)N_NODES * 16;                    // x2

    const int eg = (N_EDGES + 255) / 256;
    const int ng = (N_NODES + 255) / 256;

    // CSR build, with item_gemm at launch index 3 (ncu profiles index 3).
    zero_cnt_k<<<ng, 256>>>();                                     // 0
    hist_k<<<eg, 256>>>(adj_row);                                  // 1
    scan1_k<<<NB, SCAN_B>>>();                                     // 2
    item_gemm_k<<<(N_ITEMS + GBM - 1) / GBM, 128>>>(               // 3 <- profiled
        item_bert, bert_proj_w, (const float4*)item_emb,
        (const float4*)cat_emb, item_cat, out);
    scan2_k<<<1, 512>>>();                                         // 4
    scan3_k<<<ng, 256>>>();                                        // 5
    scatter_k<<<eg, 256>>>(adj_row, adj_col, adj_val);             // 6
    init_users_k<<<(N_USERS * 16 + 255) / 256, 256>>>(             // 7
        (const float4*)user_emb, (const float4*)gender_emb,
        (const float4*)age_emb, user_gender, user_age, out);

    const int sg = (N_NODES * 8 + 255) / 256;
    spmm_gather_k<<<sg, 256>>>(out,  buf0);          // x1 = A x0
    spmm_gather_k<<<sg, 256>>>(buf0, buf1);          // x2 = A x1
    spmm_final_k<<<sg, 256>>>(buf1, buf0, out);      // out = (x0+x1+x2+A x2)/4
}

// round 8
// speedup vs baseline: 1.7411x; 1.1380x over previous
#include <cuda_runtime.h>

#define N_USERS 200000
#define N_ITEMS 100000
#define N_NODES 300000
#define N_EDGES 1500000
#define DIM 64
#define BERT 384

#define SCAN_B 1024
#define NB ((N_NODES + SCAN_B - 1) / SCAN_B)   // 293

// Scratch (static device globals — no allocs).
__device__ float g_buf[2][(size_t)N_NODES * DIM];      // x1, x2
__device__ int   g_cnt[N_NODES];                        // degree counts -> cursors
__device__ int   g_rowptr[N_NODES + 1];
__device__ int   g_blocksum[NB];
__device__ int   g_blockoff[NB];
__device__ __align__(16) int2 g_edge[N_EDGES];          // {col, val bits}

// ---------------------------------------------------------------------------
// CSR build: zero counts -> histogram -> 2-level exclusive scan -> scatter
// ---------------------------------------------------------------------------
__global__ void zero_cnt_k()
{
    int i = blockIdx.x * blockDim.x + threadIdx.x;
    if (i < N_NODES) g_cnt[i] = 0;
}

__global__ void hist_k(const int* __restrict__ rows)
{
    int e = blockIdx.x * blockDim.x + threadIdx.x;
    if (e < N_EDGES) atomicAdd(&g_cnt[rows[e]], 1);
}

__global__ __launch_bounds__(SCAN_B) void scan1_k()
{
    __shared__ int sh[SCAN_B];
    int i = blockIdx.x * SCAN_B + threadIdx.x;
    int v = (i < N_NODES) ? g_cnt[i] : 0;
    int orig = v;
    sh[threadIdx.x] = v;
    __syncthreads();
#pragma unroll
    for (int d = 1; d < SCAN_B; d <<= 1) {
        int t = (threadIdx.x >= d) ? sh[threadIdx.x - d] : 0;
        __syncthreads();
        sh[threadIdx.x] += t;
        __syncthreads();
    }
    if (i < N_NODES) g_rowptr[i] = sh[threadIdx.x] - orig;       // exclusive in-block
    if (threadIdx.x == SCAN_B - 1) g_blocksum[blockIdx.x] = sh[threadIdx.x];
}

__global__ __launch_bounds__(512) void scan2_k()
{
    __shared__ int sh[512];
    int t = threadIdx.x;
    int v = (t < NB) ? g_blocksum[t] : 0;
    int orig = v;
    sh[t] = v;
    __syncthreads();
#pragma unroll
    for (int d = 1; d < 512; d <<= 1) {
        int u = (t >= d) ? sh[t - d] : 0;
        __syncthreads();
        sh[t] += u;
        __syncthreads();
    }
    if (t < NB) g_blockoff[t] = sh[t] - orig;                    // exclusive
    if (t == 0) g_rowptr[N_NODES] = N_EDGES;
}

__global__ void scan3_k()
{
    int i = blockIdx.x * blockDim.x + threadIdx.x;
    if (i < N_NODES) {
        int r = g_rowptr[i] + g_blockoff[i >> 10];
        g_rowptr[i] = r;
        g_cnt[i] = r;                                            // cursor for scatter
    }
}

__global__ void scatter_k(const int* __restrict__ rows,
                          const int* __restrict__ cols,
                          const float* __restrict__ vals)
{
    int e = blockIdx.x * blockDim.x + threadIdx.x;
    if (e >= N_EDGES) return;
    int r = rows[e];
    int p = atomicAdd(&g_cnt[r], 1);
    g_edge[p] = make_int2(cols[e], __float_as_int(vals[e]));
}

// ---------------------------------------------------------------------------
// User init: out[u] = user_emb[u] + gender_emb[g] + age_emb[a]
// ---------------------------------------------------------------------------
__global__ void init_users_k(const float4* __restrict__ ue,
                             const float4* __restrict__ ge,
                             const float4* __restrict__ ae,
                             const int* __restrict__ ug,
                             const int* __restrict__ ua,
                             float4* __restrict__ out)
{
    int idx = blockIdx.x * blockDim.x + threadIdx.x;
    if (idx >= N_USERS * 16) return;
    int u = idx >> 4, s = idx & 15;
    int g = ug[u];
    int a = ua[u];
    float4 r = ue[idx];
    float4 gv = ge[g * 16 + s];
    float4 av = ae[a * 16 + s];
    r.x += gv.x + av.x; r.y += gv.y + av.y;
    r.z += gv.z + av.z; r.w += gv.w + av.w;
    out[idx] = r;
}

// ---------------------------------------------------------------------------
// Item init GEMM via TF32 tensor cores (mma.sync.m16n8k8).
// BM=64, BN=64 (full), BK=16, 128 threads (4 warps).  Each warp computes a
// 16x64 slab: 8 n-tiles of m16n8, fp32 accumulators.  Smem stride 72 words
// (mod 32 == 8) -> conflict-free fragment LDS.  Double-buffered smem with
// register prefetch of next tile's globals; tf32 convert at store time.
// ---------------------------------------------------------------------------
#define GBM 64
#define GBK 16
#define NT (BERT / GBK)      // 24
#define SSTR 72

#define CVT_TF32(d, s) asm("cvt.rna.tf32.f32 %0, %1;" : "=r"(d) : "f"(s))

#define MMA_TF32(c, a0, a1, a2, a3, b0, b1)                                  \
    asm("mma.sync.aligned.m16n8k8.row.col.f32.tf32.tf32.f32 "               \
        "{%0,%1,%2,%3}, {%4,%5,%6,%7}, {%8,%9}, {%0,%1,%2,%3};"             \
        : "+f"((c)[0]), "+f"((c)[1]), "+f"((c)[2]), "+f"((c)[3])            \
        : "r"(a0), "r"(a1), "r"(a2), "r"(a3), "r"(b0), "r"(b1))

__global__ __launch_bounds__(128) void item_gemm_k(
    const float* __restrict__ bert,      // [N_ITEMS, 384]
    const float* __restrict__ W,         // [64, 384]
    const float* __restrict__ ie,        // item_emb [N_ITEMS, 64]
    const float* __restrict__ ce,        // cat_emb [11, 64]
    const int* __restrict__ cat,
    float* __restrict__ out)
{
    __shared__ unsigned As[2][GBK][SSTR];   // [buf][k][m] tf32 bits
    __shared__ unsigned Bs[2][GBK][SSTR];   // [buf][k][n] tf32 bits

    int t    = threadIdx.x;
    int wid  = t >> 5;
    int lane = t & 31;
    int gid  = lane >> 2;        // 0..7
    int tig  = lane & 3;         // 0..3
    int wrow = wid * 16;
    int rb   = blockIdx.x * GBM;

    float c[8][4];
#pragma unroll
    for (int nt = 0; nt < 8; nt++)
#pragma unroll
        for (int j = 0; j < 4; j++) c[nt][j] = 0.f;

    // Prefetch: A = 256 f4 (2/thread), B = 256 f4 (2/thread).
    float4 va[2], vb[2];

#define LOAD_AB(k0)                                                          \
    {                                                                        \
        _Pragma("unroll")                                                    \
        for (int i = 0; i < 2; i++) {                                        \
            int q = i * 128 + t;                                             \
            int m = q >> 2, kq = q & 3;                                      \
            va[i] = (rb + m < N_ITEMS)                                       \
                ? *reinterpret_cast<const float4*>(                          \
                      bert + (size_t)(rb + m) * BERT + (k0) + kq * 4)        \
                : make_float4(0.f, 0.f, 0.f, 0.f);                           \
            vb[i] = *reinterpret_cast<const float4*>(                        \
                        W + (size_t)m * BERT + (k0) + kq * 4);               \
        }                                                                    \
    }
#define STORE_AB(buf)                                                        \
    {                                                                        \
        _Pragma("unroll")                                                    \
        for (int i = 0; i < 2; i++) {                                        \
            int q = i * 128 + t;                                             \
            int m = q >> 2, kq = q & 3;                                      \
            unsigned u0, u1, u2, u3;                                         \
            CVT_TF32(u0, va[i].x); CVT_TF32(u1, va[i].y);                    \
            CVT_TF32(u2, va[i].z); CVT_TF32(u3, va[i].w);                    \
            As[buf][kq * 4 + 0][m] = u0;                                     \
            As[buf][kq * 4 + 1][m] = u1;                                     \
            As[buf][kq * 4 + 2][m] = u2;                                     \
            As[buf][kq * 4 + 3][m] = u3;                                     \
            CVT_TF32(u0, vb[i].x); CVT_TF32(u1, vb[i].y);                    \
            CVT_TF32(u2, vb[i].z); CVT_TF32(u3, vb[i].w);                    \
            Bs[buf][kq * 4 + 0][m] = u0;                                     \
            Bs[buf][kq * 4 + 1][m] = u1;                                     \
            Bs[buf][kq * 4 + 2][m] = u2;                                     \
            Bs[buf][kq * 4 + 3][m] = u3;                                     \
        }                                                                    \
    }

    LOAD_AB(0);
    STORE_AB(0);
    __syncthreads();

#pragma unroll 1
    for (int tile = 0; tile < NT; tile++) {
        int buf = tile & 1;
        if (tile + 1 < NT) LOAD_AB((tile + 1) * GBK);

#pragma unroll
        for (int kk = 0; kk < 2; kk++) {
            int kb = kk * 8;
            unsigned a0 = As[buf][kb + tig    ][wrow + gid];
            unsigned a1 = As[buf][kb + tig    ][wrow + gid + 8];
            unsigned a2 = As[buf][kb + tig + 4][wrow + gid];
            unsigned a3 = As[buf][kb + tig + 4][wrow + gid + 8];
#pragma unroll
            for (int nt = 0; nt < 8; nt++) {
                unsigned b0 = Bs[buf][kb + tig    ][nt * 8 + gid];
                unsigned b1 = Bs[buf][kb + tig + 4][nt * 8 + gid];
                MMA_TF32(c[nt], a0, a1, a2, a3, b0, b1);
            }
        }

        if (tile + 1 < NT) STORE_AB(buf ^ 1);
        __syncthreads();
    }

    // Epilogue: + item_emb + cat_emb, float2 stores.
    int r0 = rb + wrow + gid;
    int r1 = r0 + 8;
    int cc0 = (r0 < N_ITEMS) ? cat[r0] : 0;
    int cc1 = (r1 < N_ITEMS) ? cat[r1] : 0;
#pragma unroll
    for (int nt = 0; nt < 8; nt++) {
        int n0 = nt * 8 + tig * 2;
        if (r0 < N_ITEMS) {
            float2 e = *reinterpret_cast<const float2*>(ie + (size_t)r0 * 64 + n0);
            float2 v = *reinterpret_cast<const float2*>(ce + (size_t)cc0 * 64 + n0);
            float2 o = make_float2(c[nt][0] + e.x + v.x, c[nt][1] + e.y + v.y);
            *reinterpret_cast<float2*>(out + (size_t)(N_USERS + r0) * 64 + n0) = o;
        }
        if (r1 < N_ITEMS) {
            float2 e = *reinterpret_cast<const float2*>(ie + (size_t)r1 * 64 + n0);
            float2 v = *reinterpret_cast<const float2*>(ce + (size_t)cc1 * 64 + n0);
            float2 o = make_float2(c[nt][2] + e.x + v.x, c[nt][3] + e.y + v.y);
            *reinterpret_cast<float2*>(out + (size_t)(N_USERS + r1) * 64 + n0) = o;
        }
    }
}

// ---------------------------------------------------------------------------
// CSR gather SpMM (R4 best): 8 lanes per row, each lane owns 2 float4
// segments -> 2 independent loads per edge; size-stepped unrolling (4/2/1)
// keeps up to 8 x-loads in flight.
// ---------------------------------------------------------------------------
struct f4x2 { float4 a, b; };

__device__ __forceinline__ f4x2 spmm_row8(const float4* __restrict__ x,
                                          int r, int s)
{
    int beg = __ldg(&g_rowptr[r]);
    int end = __ldg(&g_rowptr[r + 1]);
    float4 acc0 = make_float4(0.f, 0.f, 0.f, 0.f);
    float4 acc1 = make_float4(0.f, 0.f, 0.f, 0.f);
    int jj = beg;
    while (jj < end) {
        int n = end - jj;
        if (n >= 4) {
            int2 e0 = __ldg(&g_edge[jj + 0]);
            int2 e1 = __ldg(&g_edge[jj + 1]);
            int2 e2 = __ldg(&g_edge[jj + 2]);
            int2 e3 = __ldg(&g_edge[jj + 3]);
            float4 p0 = __ldg(&x[e0.x * 16 + 2 * s]);
            float4 q0 = __ldg(&x[e0.x * 16 + 2 * s + 1]);
            float4 p1 = __ldg(&x[e1.x * 16 + 2 * s]);
            float4 q1 = __ldg(&x[e1.x * 16 + 2 * s + 1]);
            float4 p2 = __ldg(&x[e2.x * 16 + 2 * s]);
            float4 q2 = __ldg(&x[e2.x * 16 + 2 * s + 1]);
            float4 p3 = __ldg(&x[e3.x * 16 + 2 * s]);
            float4 q3 = __ldg(&x[e3.x * 16 + 2 * s + 1]);
            float v0 = __int_as_float(e0.y);
            float v1 = __int_as_float(e1.y);
            float v2 = __int_as_float(e2.y);
            float v3 = __int_as_float(e3.y);
            acc0.x += v0 * p0.x; acc0.y += v0 * p0.y; acc0.z += v0 * p0.z; acc0.w += v0 * p0.w;
            acc1.x += v0 * q0.x; acc1.y += v0 * q0.y; acc1.z += v0 * q0.z; acc1.w += v0 * q0.w;
            acc0.x += v1 * p1.x; acc0.y += v1 * p1.y; acc0.z += v1 * p1.z; acc0.w += v1 * p1.w;
            acc1.x += v1 * q1.x; acc1.y += v1 * q1.y; acc1.z += v1 * q1.z; acc1.w += v1 * q1.w;
            acc0.x += v2 * p2.x; acc0.y += v2 * p2.y; acc0.z += v2 * p2.z; acc0.w += v2 * p2.w;
            acc1.x += v2 * q2.x; acc1.y += v2 * q2.y; acc1.z += v2 * q2.z; acc1.w += v2 * q2.w;
            acc0.x += v3 * p3.x; acc0.y += v3 * p3.y; acc0.z += v3 * p3.z; acc0.w += v3 * p3.w;
            acc1.x += v3 * q3.x; acc1.y += v3 * q3.y; acc1.z += v3 * q3.z; acc1.w += v3 * q3.w;
            jj += 4;
        } else if (n >= 2) {
            int2 e0 = __ldg(&g_edge[jj + 0]);
            int2 e1 = __ldg(&g_edge[jj + 1]);
            float4 p0 = __ldg(&x[e0.x * 16 + 2 * s]);
            float4 q0 = __ldg(&x[e0.x * 16 + 2 * s + 1]);
            float4 p1 = __ldg(&x[e1.x * 16 + 2 * s]);
            float4 q1 = __ldg(&x[e1.x * 16 + 2 * s + 1]);
            float v0 = __int_as_float(e0.y);
            float v1 = __int_as_float(e1.y);
            acc0.x += v0 * p0.x; acc0.y += v0 * p0.y; acc0.z += v0 * p0.z; acc0.w += v0 * p0.w;
            acc1.x += v0 * q0.x; acc1.y += v0 * q0.y; acc1.z += v0 * q0.z; acc1.w += v0 * q0.w;
            acc0.x += v1 * p1.x; acc0.y += v1 * p1.y; acc0.z += v1 * p1.z; acc0.w += v1 * p1.w;
            acc1.x += v1 * q1.x; acc1.y += v1 * q1.y; acc1.z += v1 * q1.z; acc1.w += v1 * q1.w;
            jj += 2;
        } else {
            int2 e0 = __ldg(&g_edge[jj]);
            float4 p0 = __ldg(&x[e0.x * 16 + 2 * s]);
            float4 q0 = __ldg(&x[e0.x * 16 + 2 * s + 1]);
            float v0 = __int_as_float(e0.y);
            acc0.x += v0 * p0.x; acc0.y += v0 * p0.y; acc0.z += v0 * p0.z; acc0.w += v0 * p0.w;
            acc1.x += v0 * q0.x; acc1.y += v0 * q0.y; acc1.z += v0 * q0.z; acc1.w += v0 * q0.w;
            jj += 1;
        }
    }
    f4x2 r2; r2.a = acc0; r2.b = acc1;
    return r2;
}

__global__ __launch_bounds__(256) void spmm_gather_k(const float4* __restrict__ x,
                                                     float4* __restrict__ y)
{
    int tid = blockIdx.x * blockDim.x + threadIdx.x;
    int r = tid >> 3;
    if (r >= N_NODES) return;
    int s = tid & 7;
    f4x2 acc = spmm_row8(x, r, s);
    y[r * 16 + 2 * s]     = acc.a;
    y[r * 16 + 2 * s + 1] = acc.b;
}

// Last layer fused with the mean: out = (x0 + x1 + x2 + A*x2) / 4
__global__ __launch_bounds__(256) void spmm_final_k(const float4* __restrict__ x,  // x2
                                                    const float4* __restrict__ b1, // x1
                                                    float4* __restrict__ out)      // x0 in, result out
{
    int tid = blockIdx.x * blockDim.x + threadIdx.x;
    int r = tid >> 3;
    if (r >= N_NODES) return;
    int s = tid & 7;
    f4x2 acc = spmm_row8(x, r, s);
#pragma unroll
    for (int h = 0; h < 2; h++) {
        int o = r * 16 + 2 * s + h;
        float4 ac = h ? acc.b : acc.a;
        float4 a0 = out[o];
        float4 a1 = b1[o];
        float4 a2 = x[o];
        float4 v;
        v.x = (a0.x + a1.x + a2.x + ac.x) * 0.25f;
        v.y = (a0.y + a1.y + a2.y + ac.y) * 0.25f;
        v.z = (a0.z + a1.z + a2.z + ac.z) * 0.25f;
        v.w = (a0.w + a1.w + a2.w + ac.w) * 0.25f;
        out[o] = v;
    }
}

// ---------------------------------------------------------------------------
extern "C" void kernel_launch(void* const* d_in, const int* in_sizes, int n_in,
                              void* d_out, int out_size)
{
    const float* user_emb    = (const float*)d_in[0];
    const float* item_emb    = (const float*)d_in[1];
    const float* gender_emb  = (const float*)d_in[2];
    const float* age_emb     = (const float*)d_in[3];
    const float* cat_emb     = (const float*)d_in[4];
    const float* bert_proj_w = (const float*)d_in[5];
    const float* item_bert   = (const float*)d_in[6];
    const float* adj_val     = (const float*)d_in[7];
    const int*   user_gender = (const int*)d_in[8];
    const int*   user_age    = (const int*)d_in[9];
    const int*   item_cat    = (const int*)d_in[10];
    const int*   adj_row     = (const int*)d_in[11];
    const int*   adj_col     = (const int*)d_in[12];
    float4* out = (float4*)d_out;

    (void)in_sizes; (void)n_in; (void)out_size;

    float4* buf0; cudaGetSymbolAddress((void**)&buf0, g_buf);      // x1
    float4* buf1 = buf0 + (size_t)N_NODES * 16;                    // x2

    const int eg = (N_EDGES + 255) / 256;
    const int ng = (N_NODES + 255) / 256;

    // CSR build, with item_gemm at launch index 3 (ncu profiles index 3).
    zero_cnt_k<<<ng, 256>>>();                                     // 0
    hist_k<<<eg, 256>>>(adj_row);                                  // 1
    scan1_k<<<NB, SCAN_B>>>();                                     // 2
    item_gemm_k<<<(N_ITEMS + GBM - 1) / GBM, 128>>>(               // 3 <- profiled
        item_bert, bert_proj_w, item_emb, cat_emb, item_cat,
        (float*)d_out);
    scan2_k<<<1, 512>>>();                                         // 4
    scan3_k<<<ng, 256>>>();                                        // 5
    scatter_k<<<eg, 256>>>(adj_row, adj_col, adj_val);             // 6
    init_users_k<<<(N_USERS * 16 + 255) / 256, 256>>>(             // 7
        (const float4*)user_emb, (const float4*)gender_emb,
        (const float4*)age_emb, user_gender, user_age, out);

    const int sg = (N_NODES * 8 + 255) / 256;
    spmm_gather_k<<<sg, 256>>>(out,  buf0);          // x1 = A x0
    spmm_gather_k<<<sg, 256>>>(buf0, buf1);          // x2 = A x1
    spmm_final_k<<<sg, 256>>>(buf1, buf0, out);      // out = (x0+x1+x2+A x2)/4
}